// round 2
// baseline (speedup 1.0000x reference)
#include <cuda_runtime.h>

// VectorQuantizer: z [B,64] f32, codebook [1024,64] f32
// out = concat( z_q_st [B*64], vq_loss [1], indices-as-float [B] )

typedef unsigned long long u64;

#define K_CODES 1024
#define D 64
#define THREADS 256
#define ROWS_PER_CTA (2*THREADS)
#define CHUNK 256
#define NCHUNK (K_CODES/CHUNK)

__device__ double g_loss;
__device__ u64   g_cdup[K_CODES * D];  // codebook duplicated {c,c} per element
__device__ float g_c2[K_CODES];        // per-code squared norm

static __device__ __forceinline__ u64 pack2(float x, float y) {
    u64 r; asm("mov.b64 %0,{%1,%2};" : "=l"(r) : "f"(x), "f"(y)); return r;
}
static __device__ __forceinline__ void unpack2(u64 v, float& x, float& y) {
    asm("mov.b64 {%0,%1},%2;" : "=f"(x), "=f"(y) : "l"(v));
}
static __device__ __forceinline__ u64 ffma2(u64 a, u64 b, u64 c) {
    u64 d; asm("fma.rn.f32x2 %0,%1,%2,%3;" : "=l"(d) : "l"(a), "l"(b), "l"(c)); return d;
}
static __device__ __forceinline__ u64 fmul2(u64 a, u64 b) {
    u64 d; asm("mul.rn.f32x2 %0,%1,%2;" : "=l"(d) : "l"(a), "l"(b)); return d;
}
static __device__ __forceinline__ u64 fadd2(u64 a, u64 b) {
    u64 d; asm("add.rn.f32x2 %0,%1,%2;" : "=l"(d) : "l"(a), "l"(b)); return d;
}

// Build duplicated codebook + c2 (sum of elementwise squares, tree order). Also zero loss acc.
__global__ void vq_prep(const float* __restrict__ cb) {
    __shared__ float s[D];
    int k = blockIdx.x, d = threadIdx.x;
    float v = cb[k * D + d];
    g_cdup[k * D + d] = pack2(v, v);
    s[d] = v * v;
    __syncthreads();
#pragma unroll
    for (int off = D / 2; off >= 1; off >>= 1) {
        if (d < off) s[d] = s[d] + s[d + off];
        __syncthreads();
    }
    if (d == 0) {
        g_c2[k] = s[0];
        if (k == 0) g_loss = 0.0;
    }
}

__global__ void __launch_bounds__(THREADS, 1)
vq_main(const float* __restrict__ z, const float* __restrict__ cb,
        float* __restrict__ out, int B, int out_size) {
    extern __shared__ u64 sm[];
    u64* s_c  = sm;             // CHUNK*D duplicated codebook chunk
    u64* s_c2 = sm + CHUNK * D; // CHUNK duplicated c2

    const int t = threadIdx.x;
    const long base = (long)blockIdx.x * ROWS_PER_CTA;
    const long r0 = base + t;
    const long r1 = base + THREADS + t;

    // Load both rows, pack as {row0, row1} f32x2 per dim
    u64 zp[D];
    {
        const float4* a4 = (const float4*)(z + r0 * D);
        const float4* b4 = (const float4*)(z + r1 * D);
#pragma unroll
        for (int i = 0; i < D / 4; i++) {
            float4 a = a4[i], b = b4[i];
            zp[4 * i + 0] = pack2(a.x, b.x);
            zp[4 * i + 1] = pack2(a.y, b.y);
            zp[4 * i + 2] = pack2(a.z, b.z);
            zp[4 * i + 3] = pack2(a.w, b.w);
        }
    }

    // z2 = sum(z*z): elementwise square (rounded), pairwise tree sum
    u64 z2p;
    {
        u64 s[32];
#pragma unroll
        for (int i = 0; i < 32; i++)
            s[i] = fadd2(fmul2(zp[2 * i], zp[2 * i]), fmul2(zp[2 * i + 1], zp[2 * i + 1]));
#pragma unroll
        for (int off = 16; off >= 1; off >>= 1)
#pragma unroll
            for (int i = 0; i < off; i++) s[i] = fadd2(s[i], s[i + off]);
        z2p = s[0];
    }

    const u64 NEG2 = 0xC0000000C0000000ull;  // {-2.0f, -2.0f}
    float mv0 = 3.402823466e38f, mv1 = 3.402823466e38f;
    int mi0 = 0, mi1 = 0;

    for (int ch = 0; ch < NCHUNK; ++ch) {
        __syncthreads();
        const u64* src = g_cdup + (size_t)ch * CHUNK * D;
#pragma unroll 4
        for (int i = t; i < CHUNK * D; i += THREADS) s_c[i] = src[i];
        for (int i = t; i < CHUNK; i += THREADS) {
            float c2v = g_c2[ch * CHUNK + i];
            s_c2[i] = pack2(c2v, c2v);
        }
        __syncthreads();

        const int kbase = ch * CHUNK;
        for (int kk = 0; kk < CHUNK; kk++) {
            const u64* cp = s_c + kk * D;
            u64 a0 = 0, a1 = 0, a2 = 0, a3 = 0;  // 0ull == {0.f,0.f}
#pragma unroll
            for (int dd = 0; dd < D; dd += 4) {
                ulonglong2 c01 = *(const ulonglong2*)(cp + dd);
                ulonglong2 c23 = *(const ulonglong2*)(cp + dd + 2);
                a0 = ffma2(zp[dd + 0], c01.x, a0);
                a1 = ffma2(zp[dd + 1], c01.y, a1);
                a2 = ffma2(zp[dd + 2], c23.x, a2);
                a3 = ffma2(zp[dd + 3], c23.y, a3);
            }
            u64 cr = fadd2(fadd2(a0, a1), fadd2(a2, a3));
            // d = (z2 - 2*cross) + c2, each op IEEE fp32 per lane (matches jnp elementwise)
            u64 dv = fadd2(fadd2(z2p, fmul2(cr, NEG2)), s_c2[kk]);
            float d0, d1; unpack2(dv, d0, d1);
            int kidx = kbase + kk;
            if (d0 < mv0) { mv0 = d0; mi0 = kidx; }  // strict <  => first index on ties
            if (d1 < mv1) { mv1 = d1; mi1 = kidx; }
        }
    }

    // Epilogue: gather z_q, write out, accumulate loss partial
    double lacc = 0.0;
    {
        const float4* q0 = (const float4*)(cb + (size_t)mi0 * D);
        const float4* q1 = (const float4*)(cb + (size_t)mi1 * D);
        float4* o0 = (float4*)(out + r0 * D);
        float4* o1 = (float4*)(out + r1 * D);
#pragma unroll
        for (int i = 0; i < D / 4; i++) {
            float4 a = q0[i], b = q1[i];
            float zx, zy;
            unpack2(zp[4 * i + 0], zx, zy);
            { float dA = a.x - zx, dB = b.x - zy; float sA = dA * dA, sB = dB * dB; lacc += (double)sA + (double)sB; }
            unpack2(zp[4 * i + 1], zx, zy);
            { float dA = a.y - zx, dB = b.y - zy; float sA = dA * dA, sB = dB * dB; lacc += (double)sA + (double)sB; }
            unpack2(zp[4 * i + 2], zx, zy);
            { float dA = a.z - zx, dB = b.z - zy; float sA = dA * dA, sB = dB * dB; lacc += (double)sA + (double)sB; }
            unpack2(zp[4 * i + 3], zx, zy);
            { float dA = a.w - zx, dB = b.w - zy; float sA = dA * dA, sB = dB * dB; lacc += (double)sA + (double)sB; }
            o0[i] = a;
            o1[i] = b;
        }
    }

    // indices (as float) after [z_q | loss]
    if ((long)out_size >= (long)B * D + 1 + B) {
        const long iofs = (long)B * D + 1;
        out[iofs + r0] = (float)mi0;
        out[iofs + r1] = (float)mi1;
    }

    // block-reduce loss partials, one atomic per CTA
    __syncthreads();
    double* sd = (double*)sm;
    sd[t] = lacc;
    __syncthreads();
#pragma unroll
    for (int off = THREADS / 2; off >= 1; off >>= 1) {
        if (t < off) sd[t] += sd[t + off];
        __syncthreads();
    }
    if (t == 0) atomicAdd(&g_loss, sd[0]);
}

__global__ void vq_finish(float* __restrict__ out, int B, int out_size) {
    if ((long)out_size >= (long)B * D + 1) {
        float m = (float)(g_loss / (double)((long)B * D));
        out[(size_t)B * D] = m + 0.25f * m;  // codebook_loss + 0.25*commitment (same value)
    }
}

extern "C" void kernel_launch(void* const* d_in, const int* in_sizes, int n_in,
                              void* d_out, int out_size) {
    const float* z  = (const float*)d_in[0];
    const float* cb = (const float*)d_in[1];
    float* out = (float*)d_out;
    const int B = in_sizes[0] / D;

    const size_t smem = (size_t)CHUNK * D * sizeof(u64) + CHUNK * sizeof(u64);
    cudaFuncSetAttribute(vq_main, cudaFuncAttributeMaxDynamicSharedMemorySize, (int)smem);

    vq_prep<<<K_CODES, D>>>(cb);
    vq_main<<<B / ROWS_PER_CTA, THREADS, smem>>>(z, cb, out, B, out_size);
    vq_finish<<<1, 1>>>(out, B, out_size);
}

// round 3
// speedup vs baseline: 1.2459x; 1.2459x over previous
#include <cuda_runtime.h>

// VectorQuantizer: z [B,64] f32, codebook [1024,64] f32
// out = concat( z_q_st [B*64], vq_loss [1], indices-as-float [B] )

typedef unsigned long long u64;

#define K_CODES 1024
#define D 64
#define THREADS 256
#define CHUNK 256                  // codes staged in smem per pass
#define NCHUNK (K_CODES/CHUNK)
#define KB 8                       // codes per register tile (4 f32x2 pairs)

__device__ double g_loss;
__device__ float  g_ctf[D * K_CODES];  // transposed codebook: g_ctf[d*1024 + k]
__device__ float  g_c2[K_CODES];       // per-code squared norm (tree order)

static __device__ __forceinline__ u64 pack2(float x, float y) {
    u64 r; asm("mov.b64 %0,{%1,%2};" : "=l"(r) : "f"(x), "f"(y)); return r;
}
static __device__ __forceinline__ void unpack2(u64 v, float& x, float& y) {
    asm("mov.b64 {%0,%1},%2;" : "=f"(x), "=f"(y) : "l"(v));
}
static __device__ __forceinline__ u64 ffma2(u64 a, u64 b, u64 c) {
    u64 d; asm("fma.rn.f32x2 %0,%1,%2,%3;" : "=l"(d) : "l"(a), "l"(b), "l"(c)); return d;
}
static __device__ __forceinline__ u64 fmul2(u64 a, u64 b) {
    u64 d; asm("mul.rn.f32x2 %0,%1,%2;" : "=l"(d) : "l"(a), "l"(b)); return d;
}
static __device__ __forceinline__ u64 fadd2(u64 a, u64 b) {
    u64 d; asm("add.rn.f32x2 %0,%1,%2;" : "=l"(d) : "l"(a), "l"(b)); return d;
}

// Prep: transpose codebook into g_ctf, compute c2 (tree order, same as R1), zero loss.
__global__ void vq_prep(const float* __restrict__ cb) {
    __shared__ float s[D];
    int k = blockIdx.x, d = threadIdx.x;
    float v = cb[k * D + d];
    g_ctf[d * K_CODES + k] = v;
    s[d] = v * v;
    __syncthreads();
#pragma unroll
    for (int off = D / 2; off >= 1; off >>= 1) {
        if (d < off) s[d] = s[d] + s[d + off];
        __syncthreads();
    }
    if (d == 0) {
        g_c2[k] = s[0];
        if (k == 0) g_loss = 0.0;
    }
}

__global__ void __launch_bounds__(THREADS, 2)
vq_main(const float* __restrict__ z, const float* __restrict__ cb,
        float* __restrict__ out, int B, int out_size) {
    extern __shared__ float sm[];
    float* s_c  = sm;                         // [D][CHUNK] transposed chunk, plain f32
    u64*   s_c2 = (u64*)(sm + D * CHUNK);     // CHUNK/2 c2 pairs {c2_2j, c2_2j+1}

    const int t = threadIdx.x;
    const long row = (long)blockIdx.x * THREADS + t;

    // Load this thread's z row (plain floats)
    float zr[D];
    {
        const float4* a4 = (const float4*)(z + row * D);
#pragma unroll
        for (int i = 0; i < D / 4; i++) {
            float4 a = a4[i];
            zr[4 * i + 0] = a.x; zr[4 * i + 1] = a.y;
            zr[4 * i + 2] = a.z; zr[4 * i + 3] = a.w;
        }
    }

    // z2 = sum(z*z): same pairwise tree order as R1 (passed)
    float z2;
    {
        float s[32];
#pragma unroll
        for (int i = 0; i < 32; i++)
            s[i] = zr[2 * i] * zr[2 * i] + zr[2 * i + 1] * zr[2 * i + 1];
#pragma unroll
        for (int off = 16; off >= 1; off >>= 1)
#pragma unroll
            for (int i = 0; i < off; i++) s[i] = s[i] + s[i + off];
        z2 = s[0];
    }
    const u64 z2d  = pack2(z2, z2);
    const u64 NEG2 = 0xC0000000C0000000ull;  // {-2.0f, -2.0f}

    float mv = 3.402823466e38f;
    int   mi = 0;

    for (int ch = 0; ch < NCHUNK; ++ch) {
        __syncthreads();
        // Stage transposed chunk: coalesced float4 copy, conflict-free STS
        {
            const float4* src = (const float4*)g_ctf;
            float4* dst = (float4*)s_c;
#pragma unroll 4
            for (int i = t; i < D * CHUNK / 4; i += THREADS) {
                int d  = i >> 6;          // CHUNK/4 = 64 float4 per dim row
                int c4 = i & 63;
                dst[d * 64 + c4] = src[d * (K_CODES / 4) + ch * (CHUNK / 4) + c4];
            }
            if (t < CHUNK / 2) {
                float2 c2p = *(const float2*)(g_c2 + ch * CHUNK + 2 * t);
                s_c2[t] = pack2(c2p.x, c2p.y);
            }
        }
        __syncthreads();

        const int kbase = ch * CHUNK;
        for (int kb = 0; kb < CHUNK; kb += KB) {
            // 4 code-pairs x 4 FMA chains (chain = d%4, matching R1 rounding)
            u64 a0[4] = {0,0,0,0}, a1[4] = {0,0,0,0}, a2[4] = {0,0,0,0}, a3[4] = {0,0,0,0};
#pragma unroll
            for (int d = 0; d < D; d += 4) {
#pragma unroll
                for (int j = 0; j < 4; j++) {
                    float zv = zr[d + j];
                    u64 zdup = pack2(zv, zv);
                    const u64* cp = (const u64*)(s_c + (d + j) * CHUNK + kb);
                    ulonglong2 c01 = *(const ulonglong2*)cp;
                    ulonglong2 c23 = *((const ulonglong2*)cp + 1);
                    a0[j] = ffma2(zdup, c01.x, a0[j]);
                    a1[j] = ffma2(zdup, c01.y, a1[j]);
                    a2[j] = ffma2(zdup, c23.x, a2[j]);
                    a3[j] = ffma2(zdup, c23.y, a3[j]);
                }
            }
            // finalize 4 pairs: cr = (c0+c1)+(c2+c3); d = (z2 - 2cr) + c2
#pragma unroll
            for (int p = 0; p < 4; p++) {
                u64 cr = (p == 0) ? fadd2(fadd2(a0[0], a0[1]), fadd2(a0[2], a0[3]))
                       : (p == 1) ? fadd2(fadd2(a1[0], a1[1]), fadd2(a1[2], a1[3]))
                       : (p == 2) ? fadd2(fadd2(a2[0], a2[1]), fadd2(a2[2], a2[3]))
                                  : fadd2(fadd2(a3[0], a3[1]), fadd2(a3[2], a3[3]));
                u64 dv = fadd2(fadd2(z2d, fmul2(cr, NEG2)), s_c2[(kb >> 1) + p]);
                float d0, d1; unpack2(dv, d0, d1);
                int k0 = kbase + kb + 2 * p;
                if (d0 < mv) { mv = d0; mi = k0; }      // strict < => first index wins
                if (d1 < mv) { mv = d1; mi = k0 + 1; }
            }
        }
    }

    // Epilogue: gather z_q, write out, accumulate loss partial in double
    double lacc = 0.0;
    {
        const float4* q = (const float4*)(cb + (size_t)mi * D);
        float4* o = (float4*)(out + row * D);
#pragma unroll
        for (int i = 0; i < D / 4; i++) {
            float4 a = q[i];
            float dA;
            dA = a.x - zr[4 * i + 0]; lacc += (double)(dA * dA);
            dA = a.y - zr[4 * i + 1]; lacc += (double)(dA * dA);
            dA = a.z - zr[4 * i + 2]; lacc += (double)(dA * dA);
            dA = a.w - zr[4 * i + 3]; lacc += (double)(dA * dA);
            o[i] = a;
        }
    }

    if ((long)out_size >= (long)B * D + 1 + B) {
        out[(long)B * D + 1 + row] = (float)mi;
    }

    // block-reduce loss partials (reuse smem), one atomic per CTA
    __syncthreads();
    double* sd = (double*)sm;
    sd[t] = lacc;
    __syncthreads();
#pragma unroll
    for (int off = THREADS / 2; off >= 1; off >>= 1) {
        if (t < off) sd[t] += sd[t + off];
        __syncthreads();
    }
    if (t == 0) atomicAdd(&g_loss, sd[0]);
}

__global__ void vq_finish(float* __restrict__ out, int B, int out_size) {
    if ((long)out_size >= (long)B * D + 1) {
        float m = (float)(g_loss / (double)((long)B * D));
        out[(size_t)B * D] = m + 0.25f * m;  // codebook_loss + 0.25*commitment
    }
}

extern "C" void kernel_launch(void* const* d_in, const int* in_sizes, int n_in,
                              void* d_out, int out_size) {
    const float* z  = (const float*)d_in[0];
    const float* cb = (const float*)d_in[1];
    float* out = (float*)d_out;
    const int B = in_sizes[0] / D;

    const size_t smem = (size_t)D * CHUNK * sizeof(float) + (CHUNK / 2) * sizeof(u64);
    cudaFuncSetAttribute(vq_main, cudaFuncAttributeMaxDynamicSharedMemorySize, (int)smem);

    vq_prep<<<K_CODES, D>>>(cb);
    vq_main<<<B / THREADS, THREADS, smem>>>(z, cb, out, B, out_size);
    vq_finish<<<1, 1>>>(out, B, out_size);
}

// round 4
// speedup vs baseline: 1.2474x; 1.0013x over previous
#include <cuda_runtime.h>

// VectorQuantizer: z [B,64] f32, codebook [1024,64] f32
// out = concat( z_q_st [B*64], vq_loss [1], indices-as-float [B] )

typedef unsigned long long u64;

#define K_CODES 1024
#define D 64
#define THREADS 256
#define CHUNK 256                  // codes staged in smem per pass
#define NCHUNK (K_CODES/CHUNK)
#define KB 8                       // codes per register tile

__device__ double   g_loss;
__device__ unsigned g_done;
__device__ float    g_c2[K_CODES];   // per-code squared norm (pairwise tree)

static __device__ __forceinline__ u64 pack2(float x, float y) {
    u64 r; asm("mov.b64 %0,{%1,%2};" : "=l"(r) : "f"(x), "f"(y)); return r;
}
static __device__ __forceinline__ void unpack2(u64 v, float& x, float& y) {
    asm("mov.b64 {%0,%1},%2;" : "=f"(x), "=f"(y) : "l"(v));
}
static __device__ __forceinline__ u64 ffma2(u64 a, u64 b, u64 c) {
    u64 d; asm("fma.rn.f32x2 %0,%1,%2,%3;" : "=l"(d) : "l"(a), "l"(b), "l"(c)); return d;
}

// Prep: c2 (pairwise tree, bitwise same as before), zero loss + done counter.
__global__ void vq_prep(const float* __restrict__ cb) {
    __shared__ float s[D];
    int k = blockIdx.x, d = threadIdx.x;
    float v = cb[k * D + d];
    s[d] = v * v;
    __syncthreads();
#pragma unroll
    for (int off = D / 2; off >= 1; off >>= 1) {
        if (d < off) s[d] = s[d] + s[d + off];
        __syncthreads();
    }
    if (d == 0) {
        g_c2[k] = s[0];
        if (k == 0) { g_loss = 0.0; g_done = 0u; }
    }
}

__global__ void __launch_bounds__(THREADS, 2)
vq_main(const float* __restrict__ z, const float* __restrict__ cb,
        float* __restrict__ out, int B, int out_size) {
    extern __shared__ float sm[];
    float* s_c  = sm;               // [CHUNK][D] row-major codebook chunk
    float* s_c2 = sm + CHUNK * D;   // CHUNK c2 values

    const int t = threadIdx.x;
    const long row = (long)blockIdx.x * THREADS + t;

    // Load this thread's z row, packed {z_2i, z_2i+1} (one-time packing)
    u64 zp[D / 2];
    float zr[D];
    {
        const float4* a4 = (const float4*)(z + row * D);
#pragma unroll
        for (int i = 0; i < D / 4; i++) {
            float4 a = a4[i];
            zr[4 * i + 0] = a.x; zr[4 * i + 1] = a.y;
            zr[4 * i + 2] = a.z; zr[4 * i + 3] = a.w;
            zp[2 * i + 0] = pack2(a.x, a.y);
            zp[2 * i + 1] = pack2(a.z, a.w);
        }
    }

    // z2 = sum(z*z): pairwise tree (bitwise same as R1/R2 — keeps rounding)
    float z2;
    {
        float s[32];
#pragma unroll
        for (int i = 0; i < 32; i++)
            s[i] = zr[2 * i] * zr[2 * i] + zr[2 * i + 1] * zr[2 * i + 1];
#pragma unroll
        for (int off = 16; off >= 1; off >>= 1)
#pragma unroll
            for (int i = 0; i < off; i++) s[i] = s[i] + s[i + off];
        z2 = s[0];
    }

    float mv = 3.402823466e38f;
    int   mi = 0;

    for (int ch = 0; ch < NCHUNK; ++ch) {
        __syncthreads();
        // Stage codebook chunk row-major straight from global (coalesced float4)
        {
            const float4* src = (const float4*)(cb + (size_t)ch * CHUNK * D);
            float4* dst = (float4*)s_c;
#pragma unroll 4
            for (int i = t; i < CHUNK * D / 4; i += THREADS) dst[i] = src[i];
            s_c2[t] = g_c2[ch * CHUNK + t];   // CHUNK == THREADS
        }
        __syncthreads();

        const int kbase = ch * CHUNK;
        for (int kb = 0; kb < CHUNK; kb += KB) {
            u64 acc[KB];
#pragma unroll
            for (int j = 0; j < KB; j++) acc[j] = 0ull;  // {0.f,0.f}

            // even dims accumulate in lane0, odd dims in lane1
#pragma unroll
            for (int i = 0; i < D / 2; i += 2) {
#pragma unroll
                for (int j = 0; j < KB; j++) {
                    ulonglong2 c = *(const ulonglong2*)(s_c + (size_t)(kb + j) * D + 2 * i);
                    acc[j] = ffma2(zp[i],     c.x, acc[j]);
                    acc[j] = ffma2(zp[i + 1], c.y, acc[j]);
                }
            }
#pragma unroll
            for (int j = 0; j < KB; j++) {
                float e, o; unpack2(acc[j], e, o);
                float cross = e + o;
                // fl(2*cross) exact (x2 is a power of 2), so fmaf == ref's two steps
                float dv = fmaf(-2.0f, cross, z2) + s_c2[kb + j];
                int k = kbase + kb + j;
                if (dv < mv) { mv = dv; mi = k; }   // strict < => first index wins
            }
        }
    }

    // Epilogue: gather z_q, write out, loss partial in double
    double lacc = 0.0;
    {
        const float4* q = (const float4*)(cb + (size_t)mi * D);
        float4* o = (float4*)(out + row * D);
#pragma unroll
        for (int i = 0; i < D / 4; i++) {
            float4 a = q[i];
            float dA;
            dA = a.x - zr[4 * i + 0]; lacc += (double)(dA * dA);
            dA = a.y - zr[4 * i + 1]; lacc += (double)(dA * dA);
            dA = a.z - zr[4 * i + 2]; lacc += (double)(dA * dA);
            dA = a.w - zr[4 * i + 3]; lacc += (double)(dA * dA);
            o[i] = a;
        }
    }

    if ((long)out_size >= (long)B * D + 1 + B) {
        out[(long)B * D + 1 + row] = (float)mi;
    }

    // block-reduce loss partials (reuse smem), one atomic per CTA
    __syncthreads();
    double* sd = (double*)sm;
    sd[t] = lacc;
    __syncthreads();
#pragma unroll
    for (int off = THREADS / 2; off >= 1; off >>= 1) {
        if (t < off) sd[t] += sd[t + off];
        __syncthreads();
    }
    if (t == 0) {
        atomicAdd(&g_loss, sd[0]);
        __threadfence();
        unsigned v = atomicAdd(&g_done, 1u);
        if (v == gridDim.x - 1) {       // last CTA finalizes loss
            g_done = 0u;
            if ((long)out_size >= (long)B * D + 1) {
                float m = (float)(g_loss / (double)((long)B * D));
                out[(size_t)B * D] = m + 0.25f * m;
            }
        }
    }
}

extern "C" void kernel_launch(void* const* d_in, const int* in_sizes, int n_in,
                              void* d_out, int out_size) {
    const float* z  = (const float*)d_in[0];
    const float* cb = (const float*)d_in[1];
    float* out = (float*)d_out;
    const int B = in_sizes[0] / D;

    const size_t smem = (size_t)CHUNK * D * sizeof(float) + CHUNK * sizeof(float);
    cudaFuncSetAttribute(vq_main, cudaFuncAttributeMaxDynamicSharedMemorySize, (int)smem);

    vq_prep<<<K_CODES, D>>>(cb);
    vq_main<<<B / THREADS, THREADS, smem>>>(z, cb, out, B, out_size);
}

// round 5
// speedup vs baseline: 1.5127x; 1.2127x over previous
#include <cuda_runtime.h>

// VectorQuantizer: z [B,64] f32, codebook [1024,64] f32
// out = concat( z_q_st [B*64], vq_loss [1], indices-as-float [B] )

typedef unsigned long long u64;

#define K_CODES 1024
#define D 64
#define THREADS 128
#define RPT 2                       // rows per thread
#define ROWS_CTA (THREADS*RPT)      // 256
#define CHUNK 256                   // codes staged in smem per pass
#define NCHUNK (K_CODES/CHUNK)
#define KB 4                        // codes per register tile

__device__ double   g_loss;
__device__ unsigned g_done;
__device__ float    g_c2[K_CODES];  // per-code squared norm (pairwise tree)

static __device__ __forceinline__ u64 pack2(float x, float y) {
    u64 r; asm("mov.b64 %0,{%1,%2};" : "=l"(r) : "f"(x), "f"(y)); return r;
}
static __device__ __forceinline__ void unpack2(u64 v, float& x, float& y) {
    asm("mov.b64 {%0,%1},%2;" : "=f"(x), "=f"(y) : "l"(v));
}
static __device__ __forceinline__ u64 ffma2(u64 a, u64 b, u64 c) {
    u64 d; asm("fma.rn.f32x2 %0,%1,%2,%3;" : "=l"(d) : "l"(a), "l"(b), "l"(c)); return d;
}

// Prep: c2 (pairwise tree, bitwise same as before), zero loss + done counter.
__global__ void vq_prep(const float* __restrict__ cb) {
    __shared__ float s[D];
    int k = blockIdx.x, d = threadIdx.x;
    float v = cb[k * D + d];
    s[d] = v * v;
    __syncthreads();
#pragma unroll
    for (int off = D / 2; off >= 1; off >>= 1) {
        if (d < off) s[d] = s[d] + s[d + off];
        __syncthreads();
    }
    if (d == 0) {
        g_c2[k] = s[0];
        if (k == 0) { g_loss = 0.0; g_done = 0u; }
    }
}

// z2 for one row held as packed pairs {z_4i,z_4i+1},{z_4i+2,z_4i+3}:
// reproduces the reference pairwise tree bitwise.
static __device__ __forceinline__ float z2_of(const u64* zp) {
    float s[32];
#pragma unroll
    for (int i = 0; i < 16; i++) {
        float a, b, c, d;
        unpack2(zp[2 * i],     a, b);
        unpack2(zp[2 * i + 1], c, d);
        s[2 * i]     = a * a + b * b;
        s[2 * i + 1] = c * c + d * d;
    }
#pragma unroll
    for (int off = 16; off >= 1; off >>= 1)
#pragma unroll
        for (int i = 0; i < off; i++) s[i] = s[i] + s[i + off];
    return s[0];
}

__global__ void __launch_bounds__(THREADS, 2)
vq_main(const float* __restrict__ z, const float* __restrict__ cb,
        float* __restrict__ out, int B, int out_size) {
    extern __shared__ float sm[];
    float* s_c  = sm;               // [CHUNK][D] row-major codebook chunk
    float* s_c2 = sm + CHUNK * D;   // CHUNK c2 values

    const int t = threadIdx.x;
    const long base = (long)blockIdx.x * ROWS_CTA;
    const long rowA = base + t;
    const long rowB = base + THREADS + t;

    // Load both z rows packed as {z_2i, z_2i+1} pairs (64 pair-movs total, one-time)
    u64 zpA[D / 2], zpB[D / 2];
    {
        const float4* a4 = (const float4*)(z + rowA * D);
        const float4* b4 = (const float4*)(z + rowB * D);
#pragma unroll
        for (int i = 0; i < D / 4; i++) {
            float4 a = a4[i];
            zpA[2 * i + 0] = pack2(a.x, a.y);
            zpA[2 * i + 1] = pack2(a.z, a.w);
            float4 b = b4[i];
            zpB[2 * i + 0] = pack2(b.x, b.y);
            zpB[2 * i + 1] = pack2(b.z, b.w);
        }
    }
    const float z2A = z2_of(zpA);
    const float z2B = z2_of(zpB);

    float mvA = 3.402823466e38f, mvB = 3.402823466e38f;
    int   miA = 0, miB = 0;

    for (int ch = 0; ch < NCHUNK; ++ch) {
        __syncthreads();
        // Stage codebook chunk row-major straight from global (coalesced float4)
        {
            const float4* src = (const float4*)(cb + (size_t)ch * CHUNK * D);
            float4* dst = (float4*)s_c;
#pragma unroll 8
            for (int i = t; i < CHUNK * D / 4; i += THREADS) dst[i] = src[i];
#pragma unroll
            for (int i = t; i < CHUNK; i += THREADS) s_c2[i] = g_c2[ch * CHUNK + i];
        }
        __syncthreads();

        const int kbase = ch * CHUNK;
        for (int kb = 0; kb < CHUNK; kb += KB) {
            u64 accA[KB], accB[KB];
#pragma unroll
            for (int j = 0; j < KB; j++) { accA[j] = 0ull; accB[j] = 0ull; }

            // lane0 accumulates even dims, lane1 odd dims (same order as R3)
#pragma unroll
            for (int i = 0; i < D / 4; i++) {
#pragma unroll
                for (int j = 0; j < KB; j++) {
                    ulonglong2 c = *(const ulonglong2*)(s_c + (size_t)(kb + j) * D + 4 * i);
                    accA[j] = ffma2(zpA[2 * i],     c.x, accA[j]);
                    accA[j] = ffma2(zpA[2 * i + 1], c.y, accA[j]);
                    accB[j] = ffma2(zpB[2 * i],     c.x, accB[j]);
                    accB[j] = ffma2(zpB[2 * i + 1], c.y, accB[j]);
                }
            }
#pragma unroll
            for (int j = 0; j < KB; j++) {
                int k = kbase + kb + j;
                float c2v = s_c2[kb + j];
                float e, o;
                unpack2(accA[j], e, o);
                float dA = fmaf(-2.0f, e + o, z2A) + c2v;
                if (dA < mvA) { mvA = dA; miA = k; }   // strict < => first index wins
                unpack2(accB[j], e, o);
                float dB = fmaf(-2.0f, e + o, z2B) + c2v;
                if (dB < mvB) { mvB = dB; miB = k; }
            }
        }
    }

    // Epilogue: gather z_q, write out, loss partials in double
    double lacc = 0.0;
    {
        const float4* qA = (const float4*)(cb + (size_t)miA * D);
        const float4* qB = (const float4*)(cb + (size_t)miB * D);
        float4* oA = (float4*)(out + rowA * D);
        float4* oB = (float4*)(out + rowB * D);
#pragma unroll
        for (int i = 0; i < D / 4; i++) {
            float4 a = qA[i];
            float x, y, u, w, d;
            unpack2(zpA[2 * i],     x, y);
            unpack2(zpA[2 * i + 1], u, w);
            d = a.x - x; lacc += (double)(d * d);
            d = a.y - y; lacc += (double)(d * d);
            d = a.z - u; lacc += (double)(d * d);
            d = a.w - w; lacc += (double)(d * d);
            oA[i] = a;
            float4 b = qB[i];
            unpack2(zpB[2 * i],     x, y);
            unpack2(zpB[2 * i + 1], u, w);
            d = b.x - x; lacc += (double)(d * d);
            d = b.y - y; lacc += (double)(d * d);
            d = b.z - u; lacc += (double)(d * d);
            d = b.w - w; lacc += (double)(d * d);
            oB[i] = b;
        }
    }

    if ((long)out_size >= (long)B * D + 1 + B) {
        const long iofs = (long)B * D + 1;
        out[iofs + rowA] = (float)miA;
        out[iofs + rowB] = (float)miB;
    }

    // block-reduce loss partials (reuse smem), one atomic per CTA
    __syncthreads();
    double* sd = (double*)sm;
    sd[t] = lacc;
    __syncthreads();
#pragma unroll
    for (int off = THREADS / 2; off >= 1; off >>= 1) {
        if (t < off) sd[t] += sd[t + off];
        __syncthreads();
    }
    if (t == 0) {
        atomicAdd(&g_loss, sd[0]);
        __threadfence();
        unsigned v = atomicAdd(&g_done, 1u);
        if (v == gridDim.x - 1) {       // last CTA finalizes loss
            g_done = 0u;
            if ((long)out_size >= (long)B * D + 1) {
                float m = (float)(g_loss / (double)((long)B * D));
                out[(size_t)B * D] = m + 0.25f * m;
            }
        }
    }
}

extern "C" void kernel_launch(void* const* d_in, const int* in_sizes, int n_in,
                              void* d_out, int out_size) {
    const float* z  = (const float*)d_in[0];
    const float* cb = (const float*)d_in[1];
    float* out = (float*)d_out;
    const int B = in_sizes[0] / D;

    const size_t smem = (size_t)CHUNK * D * sizeof(float) + CHUNK * sizeof(float);
    cudaFuncSetAttribute(vq_main, cudaFuncAttributeMaxDynamicSharedMemorySize, (int)smem);

    vq_prep<<<K_CODES, D>>>(cb);
    vq_main<<<B / ROWS_CTA, THREADS, smem>>>(z, cb, out, B, out_size);
}